// round 6
// baseline (speedup 1.0000x reference)
#include <cuda_runtime.h>

// EdgeNet v6: single fused kernel. 512 blocks (32 edge-groups x 16 node-
// segments) stream Ro/Ri at the HBM ceiling into per-segment partials; the
// LAST block of each edge-group (atomic arrival counter) reduces the 16
// L2-hot partials and runs the MLP for its 1024 edges. No second launch.

#define N_NODES 8192
#define N_EDGES 32768
#define S_SEG   16
#define NODES_PER_SEG (N_NODES / S_SEG)      // 512
#define E4      (N_EDGES / 4)                // 8192 float4 columns
#define A_THREADS 256
#define EGRPS   (E4 / A_THREADS)             // 32 edge-groups
#define EDGES_PER_GRP (N_EDGES / EGRPS)      // 1024
#define NHID    100

// Per (segment, edge): bo(float4), bi(float4).  16 MB.
__device__ float4 g_partial[(size_t)S_SEG * N_EDGES * 2];
// Arrival counters per edge-group (BSS-zeroed; reducer resets -> replay-safe).
__device__ int g_cnt[EGRPS];

__device__ __forceinline__ void fma4(float4& a, float s, const float4& x) {
    a.x = fmaf(s, x.x, a.x);
    a.y = fmaf(s, x.y, a.y);
    a.z = fmaf(s, x.z, a.z);
    a.w = fmaf(s, x.w, a.w);
}
__device__ __forceinline__ void add4(float4& a, const float4& b) {
    a.x += b.x; a.y += b.y; a.z += b.z; a.w += b.w;
}
__device__ __forceinline__ float fast_tanh(float x) {
    float e = __expf(2.0f * x);
    return 1.0f - __fdividef(2.0f, e + 1.0f);
}

__global__ __launch_bounds__(A_THREADS, 4)
void edgenet_fused_kernel(const float* __restrict__ X,
                          const float* __restrict__ Ri,
                          const float* __restrict__ Ro,
                          const float* __restrict__ W1,
                          const float* __restrict__ b1,
                          const float* __restrict__ W2,
                          const float* __restrict__ b2,
                          float* __restrict__ out)
{
    __shared__ float4 sX[NODES_PER_SEG];            // 8 KB
    __shared__ __align__(16) float sW1t[NHID][8];
    __shared__ float sb1[NHID];
    __shared__ float sW2[NHID];
    __shared__ int sLast;

    const int tid = threadIdx.x;
    const int seg = blockIdx.y;
    const int n0  = seg * NODES_PER_SEG;

    const float4* __restrict__ X4 = (const float4*)X;
    for (int i = tid; i < NODES_PER_SEG; i += A_THREADS)
        sX[i] = X4[n0 + i];
    __syncthreads();

    const int e4 = blockIdx.x * A_THREADS + tid;
    const float4* __restrict__ ro_p = (const float4*)Ro + (size_t)n0 * E4 + e4;
    const float4* __restrict__ ri_p = (const float4*)Ri + (size_t)n0 * E4 + e4;

    float4 ao0 = {0,0,0,0}, ao1 = {0,0,0,0}, ao2 = {0,0,0,0}, ao3 = {0,0,0,0};
    float4 ai0 = {0,0,0,0}, ai1 = {0,0,0,0}, ai2 = {0,0,0,0}, ai3 = {0,0,0,0};

    #pragma unroll 4
    for (int n = 0; n < NODES_PER_SEG; ++n) {
        const float4 ro = __ldcs(&ro_p[(size_t)n * E4]);   // stream-once
        const float4 ri = __ldcs(&ri_p[(size_t)n * E4]);
        const float4 x  = sX[n];
        fma4(ao0, ro.x, x);  fma4(ao1, ro.y, x);
        fma4(ao2, ro.z, x);  fma4(ao3, ro.w, x);
        fma4(ai0, ri.x, x);  fma4(ai1, ri.y, x);
        fma4(ai2, ri.z, x);  fma4(ai3, ri.w, x);
    }

    float4* __restrict__ dst = &g_partial[((size_t)seg * N_EDGES + (size_t)e4 * 4) * 2];
    dst[0] = ao0;  dst[1] = ai0;
    dst[2] = ao1;  dst[3] = ai1;
    dst[4] = ao2;  dst[5] = ai2;
    dst[6] = ao3;  dst[7] = ai3;

    // ---- last-block election for this edge-group ----
    __threadfence();                      // partials visible before arrival
    __syncthreads();                      // all stores in block issued
    if (tid == 0)
        sLast = (atomicAdd(&g_cnt[blockIdx.x], 1) == S_SEG - 1);
    __syncthreads();
    if (!sLast) return;

    // We are the last block: all 16 segments' partials are globally visible.
    if (tid == 0) g_cnt[blockIdx.x] = 0;  // reset for next graph replay

    // Stage MLP weights.
    for (int i = tid; i < 8 * NHID; i += A_THREADS) {
        int k = i / NHID, j = i % NHID;   // W1 is [8,100] row-major
        sW1t[j][k] = W1[i];
    }
    for (int i = tid; i < NHID; i += A_THREADS) {
        sb1[i] = b1[i];
        sW2[i] = W2[i];
    }
    __syncthreads();

    const int   ebase = blockIdx.x * EDGES_PER_GRP;
    const float bias2 = b2[0];

    #pragma unroll
    for (int q = 0; q < EDGES_PER_GRP / A_THREADS; ++q) {   // 4 edges/thread
        const int e = ebase + q * A_THREADS + tid;          // coalesced

        float4 ao = {0,0,0,0}, ai = {0,0,0,0};
        float4 ao2 = {0,0,0,0}, ai2 = {0,0,0,0};
        #pragma unroll
        for (int s = 0; s < S_SEG; s += 2) {
            const float4* pA = &g_partial[((size_t)s * N_EDGES + e) * 2];
            const float4* pB = &g_partial[((size_t)(s + 1) * N_EDGES + e) * 2];
            float4 a0 = pA[0], a1 = pA[1];
            float4 b0 = pB[0], b1v = pB[1];
            add4(ao, a0);   add4(ai, a1);
            add4(ao2, b0);  add4(ai2, b1v);
        }
        add4(ao, ao2);
        add4(ai, ai2);

        float acc = bias2;
        #pragma unroll 4
        for (int j = 0; j < NHID; ++j) {
            const float4 w0 = *(const float4*)&sW1t[j][0];
            const float4 w1 = *(const float4*)&sW1t[j][4];
            float s = sb1[j];
            s = fmaf(ao.x, w0.x, s);
            s = fmaf(ao.y, w0.y, s);
            s = fmaf(ao.z, w0.z, s);
            s = fmaf(ao.w, w0.w, s);
            s = fmaf(ai.x, w1.x, s);
            s = fmaf(ai.y, w1.y, s);
            s = fmaf(ai.z, w1.z, s);
            s = fmaf(ai.w, w1.w, s);
            acc = fmaf(fast_tanh(s), sW2[j], acc);
        }
        out[e] = __fdividef(1.0f, 1.0f + __expf(-acc));
    }
}

extern "C" void kernel_launch(void* const* d_in, const int* in_sizes, int n_in,
                              void* d_out, int out_size)
{
    // metadata order: X, Ri, Ro, W1, b1, W2, b2
    const float* X  = (const float*)d_in[0];
    const float* Ri = (const float*)d_in[1];
    const float* Ro = (const float*)d_in[2];
    const float* W1 = (const float*)d_in[3];
    const float* b1 = (const float*)d_in[4];
    const float* W2 = (const float*)d_in[5];
    const float* b2 = (const float*)d_in[6];
    float* out = (float*)d_out;

    dim3 grid(EGRPS, S_SEG);               // 32 x 16 = 512 blocks of 256 thr
    edgenet_fused_kernel<<<grid, A_THREADS>>>(X, Ri, Ro, W1, b1, W2, b2, out);
}

// round 7
// speedup vs baseline: 1.0966x; 1.0966x over previous
#include <cuda_runtime.h>

// EdgeNet v7: phase-1 = R5 (best, HBM-ceiling 6.99 TB/s). phase-2 rebuilt:
// 8 threads/edge, 1024 blocks, partial loads prefetched ahead of weight
// staging, MLP split 8 ways + smem combines.

#define N_NODES 8192
#define N_EDGES 32768
#define S_SEG   16
#define NODES_PER_SEG (N_NODES / S_SEG)      // 512
#define E4      (N_EDGES / 4)                // 8192 float4 columns
#define A_THREADS 256
#define EGRPS   (E4 / A_THREADS)             // 32 edge-group blocks
#define NHID    100

#define M_THREADS 256
#define EPB2     32                          // edges per phase-2 block
#define SUBS     8                           // threads per edge
#define SEGS_PER_SUB (S_SEG / SUBS)          // 2

// Per (segment, edge): bo(float4), bi(float4).  16 MB.
__device__ float4 g_partial[(size_t)S_SEG * N_EDGES * 2];

__device__ __forceinline__ void fma4(float4& a, float s, const float4& x) {
    a.x = fmaf(s, x.x, a.x);
    a.y = fmaf(s, x.y, a.y);
    a.z = fmaf(s, x.z, a.z);
    a.w = fmaf(s, x.w, a.w);
}
__device__ __forceinline__ void add4(float4& a, const float4& b) {
    a.x += b.x; a.y += b.y; a.z += b.z; a.w += b.w;
}
__device__ __forceinline__ float fast_tanh(float x) {
    float e = __expf(2.0f * x);
    return 1.0f - __fdividef(2.0f, e + 1.0f);
}

__global__ __launch_bounds__(A_THREADS, 4)
void edgenet_accum_kernel(const float* __restrict__ X,
                          const float* __restrict__ Ri,
                          const float* __restrict__ Ro)
{
    __shared__ float4 sX[NODES_PER_SEG];   // 8 KB

    const int tid = threadIdx.x;
    const int seg = blockIdx.y;
    const int n0  = seg * NODES_PER_SEG;

    const float4* __restrict__ X4 = (const float4*)X;
    for (int i = tid; i < NODES_PER_SEG; i += A_THREADS)
        sX[i] = X4[n0 + i];
    __syncthreads();

    const int e4 = blockIdx.x * A_THREADS + tid;
    const float4* __restrict__ ro_p = (const float4*)Ro + (size_t)n0 * E4 + e4;
    const float4* __restrict__ ri_p = (const float4*)Ri + (size_t)n0 * E4 + e4;

    float4 ao0 = {0,0,0,0}, ao1 = {0,0,0,0}, ao2 = {0,0,0,0}, ao3 = {0,0,0,0};
    float4 ai0 = {0,0,0,0}, ai1 = {0,0,0,0}, ai2 = {0,0,0,0}, ai3 = {0,0,0,0};

    #pragma unroll 4
    for (int n = 0; n < NODES_PER_SEG; ++n) {
        const float4 ro = __ldcs(&ro_p[(size_t)n * E4]);   // stream-once
        const float4 ri = __ldcs(&ri_p[(size_t)n * E4]);
        const float4 x  = sX[n];
        fma4(ao0, ro.x, x);  fma4(ao1, ro.y, x);
        fma4(ao2, ro.z, x);  fma4(ao3, ro.w, x);
        fma4(ai0, ri.x, x);  fma4(ai1, ri.y, x);
        fma4(ai2, ri.z, x);  fma4(ai3, ri.w, x);
    }

    float4* __restrict__ dst = &g_partial[((size_t)seg * N_EDGES + (size_t)e4 * 4) * 2];
    dst[0] = ao0;  dst[1] = ai0;
    dst[2] = ao1;  dst[3] = ai1;
    dst[4] = ao2;  dst[5] = ai2;
    dst[6] = ao3;  dst[7] = ai3;
}

__global__ __launch_bounds__(M_THREADS)
void edgenet_mlp_kernel(const float* __restrict__ W1,
                        const float* __restrict__ b1,
                        const float* __restrict__ W2,
                        const float* __restrict__ b2,
                        float* __restrict__ out)
{
    __shared__ __align__(16) float sW1t[NHID][8];   // W1 transposed [j][k]
    __shared__ float sb1[NHID];
    __shared__ float sW2[NHID];
    __shared__ float sPart[SUBS][EPB2][9];          // 9: conflict-free pad
    __shared__ float sAcc[SUBS][EPB2];

    const int tid = threadIdx.x;
    const int el  = tid & (EPB2 - 1);               // edge within block
    const int sub = tid >> 5;                       // 0..7 (warp-uniform)
    const int e   = blockIdx.x * EPB2 + el;

    // ---- Prefetch this thread's 2 segments FIRST (overlap DRAM latency) ----
    const int s0 = sub * SEGS_PER_SUB;
    const float4* p0 = &g_partial[((size_t)s0 * N_EDGES + e) * 2];
    const float4* p1 = &g_partial[((size_t)(s0 + 1) * N_EDGES + e) * 2];
    float4 a0 = p0[0], a1 = p0[1];
    float4 c0 = p1[0], c1 = p1[1];

    // ---- Weight staging (overlaps the loads above) ----
    for (int i = tid; i < 8 * NHID; i += M_THREADS) {
        int k = i / NHID, j = i % NHID;             // W1 is [8,100] row-major
        sW1t[j][k] = W1[i];
    }
    for (int i = tid; i < NHID; i += M_THREADS) {
        sb1[i] = b1[i];
        sW2[i] = W2[i];
    }

    add4(a0, c0);
    add4(a1, c1);
    sPart[sub][el][0] = a0.x;  sPart[sub][el][1] = a0.y;
    sPart[sub][el][2] = a0.z;  sPart[sub][el][3] = a0.w;
    sPart[sub][el][4] = a1.x;  sPart[sub][el][5] = a1.y;
    sPart[sub][el][6] = a1.z;  sPart[sub][el][7] = a1.w;
    __syncthreads();

    // Rebuild full 8-float edge feature.
    float B[8];
    #pragma unroll
    for (int f = 0; f < 8; ++f) {
        float t0 = sPart[0][el][f] + sPart[1][el][f];
        float t1 = sPart[2][el][f] + sPart[3][el][f];
        float t2 = sPart[4][el][f] + sPart[5][el][f];
        float t3 = sPart[6][el][f] + sPart[7][el][f];
        B[f] = (t0 + t1) + (t2 + t3);
    }

    // MLP split: sub<4 -> 13 units starting at 13*sub; sub>=4 -> 12 units at 12*sub+4.
    const int start = (sub < 4) ? 13 * sub : 12 * sub + 4;
    const int len   = (sub < 4) ? 13 : 12;
    float acc = 0.0f;
    #pragma unroll
    for (int k = 0; k < 13; ++k) {
        if (k < len) {
            const int j = start + k;
            const float4 w0 = *(const float4*)&sW1t[j][0];
            const float4 w1 = *(const float4*)&sW1t[j][4];
            float s = sb1[j];
            s = fmaf(B[0], w0.x, s);
            s = fmaf(B[1], w0.y, s);
            s = fmaf(B[2], w0.z, s);
            s = fmaf(B[3], w0.w, s);
            s = fmaf(B[4], w1.x, s);
            s = fmaf(B[5], w1.y, s);
            s = fmaf(B[6], w1.z, s);
            s = fmaf(B[7], w1.w, s);
            acc = fmaf(fast_tanh(s), sW2[j], acc);
        }
    }
    sAcc[sub][el] = acc;
    __syncthreads();

    if (tid < EPB2) {
        float t0 = sAcc[0][tid] + sAcc[1][tid];
        float t1 = sAcc[2][tid] + sAcc[3][tid];
        float t2 = sAcc[4][tid] + sAcc[5][tid];
        float t3 = sAcc[6][tid] + sAcc[7][tid];
        float a = b2[0] + (t0 + t1) + (t2 + t3);
        out[blockIdx.x * EPB2 + tid] = __fdividef(1.0f, 1.0f + __expf(-a));
    }
}

extern "C" void kernel_launch(void* const* d_in, const int* in_sizes, int n_in,
                              void* d_out, int out_size)
{
    // metadata order: X, Ri, Ro, W1, b1, W2, b2
    const float* X  = (const float*)d_in[0];
    const float* Ri = (const float*)d_in[1];
    const float* Ro = (const float*)d_in[2];
    const float* W1 = (const float*)d_in[3];
    const float* b1 = (const float*)d_in[4];
    const float* W2 = (const float*)d_in[5];
    const float* b2 = (const float*)d_in[6];
    float* out = (float*)d_out;

    dim3 grid1(EGRPS, S_SEG);              // 32 x 16 = 512 blocks of 256 thr
    edgenet_accum_kernel<<<grid1, A_THREADS>>>(X, Ri, Ro);

    dim3 grid2(N_EDGES / EPB2);            // 1024 blocks of 256 thr
    edgenet_mlp_kernel<<<grid2, M_THREADS>>>(W1, b1, W2, b2, out);
}